// round 1
// baseline (speedup 1.0000x reference)
#include <cuda_runtime.h>
#include <cstdint>

#define LRELU_SLOPE 0.2f
#define BN_EPS 1e-5f

// Problem constants (B=2, Nr=40962 icosphere level)
constexpr int  BB  = 2;
constexpr int  NR  = 40962;
constexpr int  NH  = 4 * NR - 6;      // 163842
constexpr int  CIN = 128;
constexpr int  CO  = 64;
constexpr int  NUP = 7 * CO;          // 448
constexpr long MUP = (long)BB * NR;   // 81924 rows of up-GEMM
constexpr long MC  = (long)BB * NH;   // 327684 rows of conv GEMMs
constexpr int  NPART = 512;

// Scratch (static device globals -- no allocations allowed)
__device__ float g_h  [(size_t)BB * NR * 7 * CO];  // up-proj output (B, Nr*7, 64)
__device__ float g_xup[(size_t)BB * NH * CO];      // x1_up (B, Nh, 64)
__device__ float g_y  [(size_t)BB * NH * CO];      // conv1 raw output
__device__ float g_part[NPART * 128];              // per-block partial sums/sumsq
__device__ float g_bn  [128];                      // [0:64) scale, [64:128) shift

// ---------------------------------------------------------------------------
// GEMM 1: up-projection.  C(m, col) = x1(m, :) @ up_W(:, col) + up_b
// M = 81924, K = 128, N = 448.  Tile 128x64, BK=64.
// ---------------------------------------------------------------------------
__global__ __launch_bounds__(256) void gemm_up(
    const float* __restrict__ A, const float* __restrict__ W,
    const float* __restrict__ bias)
{
    __shared__ float As[64][128];   // transposed A tile
    __shared__ float Bs[64][64];
    const int  tid     = threadIdx.x;
    const long rowBase = (long)blockIdx.x * 128;
    const int  colBase = blockIdx.y * 64;
    const int  tx = tid & 15, ty = tid >> 4;

    float acc[8][4];
#pragma unroll
    for (int i = 0; i < 8; i++)
#pragma unroll
        for (int j = 0; j < 4; j++) acc[i][j] = 0.f;

    for (int kc = 0; kc < CIN / 64; kc++) {
#pragma unroll
        for (int it = 0; it < 8; it++) {
            int  idx = it * 256 + tid;
            int  r   = idx & 127;
            int  q   = idx >> 7;
            long m   = rowBase + r;
            float4 v = make_float4(0.f, 0.f, 0.f, 0.f);
            if (m < MUP)
                v = *(const float4*)(A + m * CIN + kc * 64 + q * 4);
            As[q*4+0][r] = v.x; As[q*4+1][r] = v.y;
            As[q*4+2][r] = v.z; As[q*4+3][r] = v.w;
        }
#pragma unroll
        for (int it = 0; it < 4; it++) {
            int idx = it * 256 + tid;
            int kr  = idx >> 4;
            int q   = idx & 15;
            *(float4*)&Bs[kr][q*4] =
                *(const float4*)(W + (long)(kc*64 + kr) * NUP + colBase + q*4);
        }
        __syncthreads();
#pragma unroll 8
        for (int kk = 0; kk < 64; kk++) {
            float a[8], b[4];
            *(float4*)&a[0] = *(float4*)&As[kk][ty*8];
            *(float4*)&a[4] = *(float4*)&As[kk][ty*8 + 4];
            *(float4*)&b[0] = *(float4*)&Bs[kk][tx*4];
#pragma unroll
            for (int i = 0; i < 8; i++)
#pragma unroll
                for (int j = 0; j < 4; j++) acc[i][j] = fmaf(a[i], b[j], acc[i][j]);
        }
        __syncthreads();
    }

    float4 bi = *(const float4*)(bias + colBase + tx*4);
#pragma unroll
    for (int i = 0; i < 8; i++) {
        long m = rowBase + ty*8 + i;
        if (m < MUP) {
            float4 v = make_float4(acc[i][0] + bi.x, acc[i][1] + bi.y,
                                   acc[i][2] + bi.z, acc[i][3] + bi.w);
            *(float4*)(g_h + m * NUP + colBase + tx*4) = v;
        }
    }
}

// ---------------------------------------------------------------------------
// Build x1_up: top gather + down pair-mean, from g_h into g_xup.
// ---------------------------------------------------------------------------
__global__ void build_xup(const int* __restrict__ topi, const int* __restrict__ downi)
{
    long idx = (long)blockIdx.x * blockDim.x + threadIdx.x;
    long total = (long)BB * NH * 16;        // float4 quads
    if (idx >= total) return;
    long row = idx >> 4;
    int  q   = (int)(idx & 15);
    int  b   = (int)(row / NH);
    int  n   = (int)(row - (long)b * NH);
    const float* hb = g_h + (long)b * NR * 7 * CO;
    float4 v;
    if (n < NR) {
        int s = __ldg(topi + n);
        v = *(const float4*)(hb + (long)s * CO + q*4);
    } else {
        int m2 = n - NR;
        int s0 = __ldg(downi + 2*m2);
        int s1 = __ldg(downi + 2*m2 + 1);
        float4 a = *(const float4*)(hb + (long)s0 * CO + q*4);
        float4 c = *(const float4*)(hb + (long)s1 * CO + q*4);
        v = make_float4(0.5f*(a.x+c.x), 0.5f*(a.y+c.y),
                        0.5f*(a.z+c.z), 0.5f*(a.w+c.w));
    }
    *(float4*)(g_xup + row * CO + q*4) = v;
}

// ---------------------------------------------------------------------------
// GEMM 2: conv1 with on-the-fly neighbor gather.
// A(m, j*128+c) = concat(x1_up, x2)[b, neigh[n][j], c];  W1 (896, 64).
// ---------------------------------------------------------------------------
__global__ __launch_bounds__(256) void gemm_conv1(
    const float* __restrict__ x2, const int* __restrict__ neigh,
    const float* __restrict__ W, const float* __restrict__ bias)
{
    __shared__ float As[64][128];
    __shared__ float Bs[64][64];
    const int  tid     = threadIdx.x;
    const long rowBase = (long)blockIdx.x * 128;
    const int  tx = tid & 15, ty = tid >> 4;

    float acc[8][4];
#pragma unroll
    for (int i = 0; i < 8; i++)
#pragma unroll
        for (int j = 0; j < 4; j++) acc[i][j] = 0.f;

    for (int kc = 0; kc < 14; kc++) {
        const int j    = kc >> 1;
        const int half = kc & 1;
        const float* src = half ? x2 : g_xup;
#pragma unroll
        for (int it = 0; it < 8; it++) {
            int  idx = it * 256 + tid;
            int  r   = idx & 127;
            int  q   = idx >> 7;
            long m   = rowBase + r;
            float4 v = make_float4(0.f, 0.f, 0.f, 0.f);
            if (m < MC) {
                int b  = (int)(m / NH);
                int n  = (int)(m - (long)b * NH);
                int nb = __ldg(neigh + n*7 + j);
                v = *(const float4*)(src + ((long)b * NH + nb) * CO + q*4);
            }
            As[q*4+0][r] = v.x; As[q*4+1][r] = v.y;
            As[q*4+2][r] = v.z; As[q*4+3][r] = v.w;
        }
#pragma unroll
        for (int it = 0; it < 4; it++) {
            int idx = it * 256 + tid;
            int kr  = idx >> 4;
            int q   = idx & 15;
            *(float4*)&Bs[kr][q*4] =
                *(const float4*)(W + (long)(kc*64 + kr) * CO + q*4);
        }
        __syncthreads();
#pragma unroll 8
        for (int kk = 0; kk < 64; kk++) {
            float a[8], b[4];
            *(float4*)&a[0] = *(float4*)&As[kk][ty*8];
            *(float4*)&a[4] = *(float4*)&As[kk][ty*8 + 4];
            *(float4*)&b[0] = *(float4*)&Bs[kk][tx*4];
#pragma unroll
            for (int i = 0; i < 8; i++)
#pragma unroll
                for (int jj = 0; jj < 4; jj++) acc[i][jj] = fmaf(a[i], b[jj], acc[i][jj]);
        }
        __syncthreads();
    }

    float4 bi = *(const float4*)(bias + tx*4);
#pragma unroll
    for (int i = 0; i < 8; i++) {
        long m = rowBase + ty*8 + i;
        if (m < MC) {
            float4 v = make_float4(acc[i][0] + bi.x, acc[i][1] + bi.y,
                                   acc[i][2] + bi.z, acc[i][3] + bi.w);
            *(float4*)(g_y + m * CO + tx*4) = v;
        }
    }
}

// ---------------------------------------------------------------------------
// GEMM 3: conv2; BN1 + leaky-relu fused into the gather load of g_y.
// ---------------------------------------------------------------------------
__global__ __launch_bounds__(256) void gemm_conv2(
    const int* __restrict__ neigh, const float* __restrict__ W,
    const float* __restrict__ bias, float* __restrict__ out)
{
    __shared__ float As[64][128];
    __shared__ float Bs[64][64];
    const int  tid     = threadIdx.x;
    const long rowBase = (long)blockIdx.x * 128;
    const int  tx = tid & 15, ty = tid >> 4;

    float acc[8][4];
#pragma unroll
    for (int i = 0; i < 8; i++)
#pragma unroll
        for (int j = 0; j < 4; j++) acc[i][j] = 0.f;

    for (int j = 0; j < 7; j++) {
#pragma unroll
        for (int it = 0; it < 8; it++) {
            int  idx = it * 256 + tid;
            int  r   = idx & 127;
            int  q   = idx >> 7;
            long m   = rowBase + r;
            float4 v = make_float4(0.f, 0.f, 0.f, 0.f);
            if (m < MC) {
                int b  = (int)(m / NH);
                int n  = (int)(m - (long)b * NH);
                int nb = __ldg(neigh + n*7 + j);
                v = *(const float4*)(g_y + ((long)b * NH + nb) * CO + q*4);
                float4 sc = *(const float4*)&g_bn[q*4];
                float4 sh = *(const float4*)&g_bn[64 + q*4];
                v.x = fmaf(v.x, sc.x, sh.x); v.x = v.x >= 0.f ? v.x : LRELU_SLOPE * v.x;
                v.y = fmaf(v.y, sc.y, sh.y); v.y = v.y >= 0.f ? v.y : LRELU_SLOPE * v.y;
                v.z = fmaf(v.z, sc.z, sh.z); v.z = v.z >= 0.f ? v.z : LRELU_SLOPE * v.z;
                v.w = fmaf(v.w, sc.w, sh.w); v.w = v.w >= 0.f ? v.w : LRELU_SLOPE * v.w;
            }
            As[q*4+0][r] = v.x; As[q*4+1][r] = v.y;
            As[q*4+2][r] = v.z; As[q*4+3][r] = v.w;
        }
#pragma unroll
        for (int it = 0; it < 4; it++) {
            int idx = it * 256 + tid;
            int kr  = idx >> 4;
            int q   = idx & 15;
            *(float4*)&Bs[kr][q*4] =
                *(const float4*)(W + (long)(j*64 + kr) * CO + q*4);
        }
        __syncthreads();
#pragma unroll 8
        for (int kk = 0; kk < 64; kk++) {
            float a[8], b[4];
            *(float4*)&a[0] = *(float4*)&As[kk][ty*8];
            *(float4*)&a[4] = *(float4*)&As[kk][ty*8 + 4];
            *(float4*)&b[0] = *(float4*)&Bs[kk][tx*4];
#pragma unroll
            for (int i = 0; i < 8; i++)
#pragma unroll
                for (int jj = 0; jj < 4; jj++) acc[i][jj] = fmaf(a[i], b[jj], acc[i][jj]);
        }
        __syncthreads();
    }

    float4 bi = *(const float4*)(bias + tx*4);
#pragma unroll
    for (int i = 0; i < 8; i++) {
        long m = rowBase + ty*8 + i;
        if (m < MC) {
            float4 v = make_float4(acc[i][0] + bi.x, acc[i][1] + bi.y,
                                   acc[i][2] + bi.z, acc[i][3] + bi.w);
            *(float4*)(out + m * CO + tx*4) = v;
        }
    }
}

// ---------------------------------------------------------------------------
// Deterministic BN statistics: per-block partials, then single-block finalize.
// ---------------------------------------------------------------------------
__global__ void reduce_stats(const float* __restrict__ data, long Mrows)
{
    __shared__ float sh[2][4][64];
    int c  = threadIdx.x & 63;
    int rg = threadIdx.x >> 6;
    float s = 0.f, ss = 0.f;
    for (long r = (long)blockIdx.x * 4 + rg; r < Mrows; r += (long)gridDim.x * 4) {
        float v = data[r * 64 + c];
        s += v; ss = fmaf(v, v, ss);
    }
    sh[0][rg][c] = s; sh[1][rg][c] = ss;
    __syncthreads();
    if (rg == 0) {
        s  = sh[0][0][c] + sh[0][1][c] + sh[0][2][c] + sh[0][3][c];
        ss = sh[1][0][c] + sh[1][1][c] + sh[1][2][c] + sh[1][3][c];
        g_part[blockIdx.x * 128 + c]      = s;
        g_part[blockIdx.x * 128 + 64 + c] = ss;
    }
}

__global__ void bn_finalize(const float* __restrict__ gamma,
                            const float* __restrict__ beta, float invM)
{
    int c = threadIdx.x;   // 0..63
    float s = 0.f, ss = 0.f;
    for (int p = 0; p < NPART; p++) {
        s  += g_part[p * 128 + c];
        ss += g_part[p * 128 + 64 + c];
    }
    float mean = s * invM;
    float var  = fmaf(-mean, mean, ss * invM);
    float sc   = gamma[c] * rsqrtf(var + BN_EPS);
    g_bn[c]      = sc;
    g_bn[64 + c] = beta[c] - mean * sc;
}

__global__ void apply_bn(float* __restrict__ out)
{
    long idx = (long)blockIdx.x * blockDim.x + threadIdx.x;
    if (idx >= MC * 16) return;
    int q = (int)(idx & 15);
    float4 v  = ((float4*)out)[idx];
    float4 sc = *(const float4*)&g_bn[q*4];
    float4 sh = *(const float4*)&g_bn[64 + q*4];
    v.x = fmaf(v.x, sc.x, sh.x); v.x = v.x >= 0.f ? v.x : LRELU_SLOPE * v.x;
    v.y = fmaf(v.y, sc.y, sh.y); v.y = v.y >= 0.f ? v.y : LRELU_SLOPE * v.y;
    v.z = fmaf(v.z, sc.z, sh.z); v.z = v.z >= 0.f ? v.z : LRELU_SLOPE * v.z;
    v.w = fmaf(v.w, sc.w, sh.w); v.w = v.w >= 0.f ? v.w : LRELU_SLOPE * v.w;
    ((float4*)out)[idx] = v;
}

// ---------------------------------------------------------------------------
extern "C" void kernel_launch(void* const* d_in, const int* in_sizes, int n_in,
                              void* d_out, int out_size)
{
    const float* x1    = (const float*)d_in[0];
    const float* x2    = (const float*)d_in[1];
    const int*   neigh = (const int*)  d_in[2];
    const int*   topi  = (const int*)  d_in[3];
    const int*   downi = (const int*)  d_in[4];
    const float* upW   = (const float*)d_in[5];
    const float* upb   = (const float*)d_in[6];
    const float* W1    = (const float*)d_in[7];
    const float* b1    = (const float*)d_in[8];
    const float* g1    = (const float*)d_in[9];
    const float* be1   = (const float*)d_in[10];
    const float* W2    = (const float*)d_in[11];
    const float* b2    = (const float*)d_in[12];
    const float* g2    = (const float*)d_in[13];
    const float* be2   = (const float*)d_in[14];
    float* out = (float*)d_out;

    void* yp = nullptr;
    cudaGetSymbolAddress(&yp, g_y);

    const int gemmBlocksUp = (int)((MUP + 127) / 128);
    const int gemmBlocksC  = (int)((MC  + 127) / 128);
    const long quads       = (long)BB * NH * 16;
    const int ewBlocks     = (int)((quads + 255) / 256);

    gemm_up   <<<dim3(gemmBlocksUp, 7), 256>>>(x1, upW, upb);
    build_xup <<<ewBlocks, 256>>>(topi, downi);
    gemm_conv1<<<gemmBlocksC, 256>>>(x2, neigh, W1, b1);
    reduce_stats<<<NPART, 256>>>((const float*)yp, MC);
    bn_finalize <<<1, 64>>>(g1, be1, 1.0f / (float)MC);
    gemm_conv2<<<gemmBlocksC, 256>>>(neigh, W2, b2, out);
    reduce_stats<<<NPART, 256>>>(out, MC);
    bn_finalize <<<1, 64>>>(g2, be2, 1.0f / (float)MC);
    apply_bn  <<<ewBlocks, 256>>>(out);
}

// round 2
// speedup vs baseline: 1.0505x; 1.0505x over previous
#include <cuda_runtime.h>
#include <cstdint>

#define LRELU_SLOPE 0.2f
#define BN_EPS 1e-5f

constexpr int  BB  = 2;
constexpr int  NR  = 40962;
constexpr int  NH  = 4 * NR - 6;      // 163842
constexpr int  CIN = 128;
constexpr int  CO  = 64;
constexpr int  NUP = 7 * CO;          // 448
constexpr long MUP = (long)BB * NR;   // 81924
constexpr long MC  = (long)BB * NH;   // 327684
constexpr int  NPART = 512;

__device__ float g_h  [(size_t)BB * NR * 7 * CO];
__device__ float g_xup[(size_t)BB * NH * CO];
__device__ float g_y  [(size_t)BB * NH * CO];
__device__ float g_part[NPART * 128];
__device__ float g_bn  [128];

// ---- packed f32x2 helpers (FFMA2 path, sm_103a) ----------------------------
#define PACK_DUP(d, s) \
    asm("mov.b64 %0, {%1, %1};" : "=l"(d) : "f"(s))
#define FMA2(acc, a, b) \
    asm("fma.rn.f32x2 %0, %1, %2, %0;" : "+l"(acc) : "l"(a), "l"(b))
#define UNPACK2(lo, hi, v) \
    asm("mov.b64 {%0, %1}, %2;" : "=f"(lo), "=f"(hi) : "l"(v))

// Microkernel body: 64 k-steps over As(64x128 transposed) x Bs(64x64).
// acc[4][4]: packed pairs of rows (ty*8+2i, ty*8+2i+1), cols tx*4+j.
#define MICRO_KERNEL(As, Bs, acc, tx, ty)                                   \
    _Pragma("unroll 8")                                                     \
    for (int kk = 0; kk < 64; kk++) {                                       \
        ulonglong2 a01 = *(const ulonglong2*)&As[kk][(ty)*8];               \
        ulonglong2 a23 = *(const ulonglong2*)&As[kk][(ty)*8 + 4];           \
        float4 bv = *(const float4*)&Bs[kk][(tx)*4];                        \
        unsigned long long bd0, bd1, bd2, bd3;                              \
        PACK_DUP(bd0, bv.x); PACK_DUP(bd1, bv.y);                           \
        PACK_DUP(bd2, bv.z); PACK_DUP(bd3, bv.w);                           \
        FMA2(acc[0][0], a01.x, bd0); FMA2(acc[0][1], a01.x, bd1);           \
        FMA2(acc[0][2], a01.x, bd2); FMA2(acc[0][3], a01.x, bd3);           \
        FMA2(acc[1][0], a01.y, bd0); FMA2(acc[1][1], a01.y, bd1);           \
        FMA2(acc[1][2], a01.y, bd2); FMA2(acc[1][3], a01.y, bd3);           \
        FMA2(acc[2][0], a23.x, bd0); FMA2(acc[2][1], a23.x, bd1);           \
        FMA2(acc[2][2], a23.x, bd2); FMA2(acc[2][3], a23.x, bd3);           \
        FMA2(acc[3][0], a23.y, bd0); FMA2(acc[3][1], a23.y, bd1);           \
        FMA2(acc[3][2], a23.y, bd2); FMA2(acc[3][3], a23.y, bd3);           \
    }

#define EPILOGUE_STORE(dst, ldc, rowBase, Mlim, bi, acc, tx, ty)            \
    _Pragma("unroll")                                                       \
    for (int i2 = 0; i2 < 4; i2++) {                                        \
        float lo0, hi0, lo1, hi1, lo2, hi2, lo3, hi3;                       \
        UNPACK2(lo0, hi0, acc[i2][0]); UNPACK2(lo1, hi1, acc[i2][1]);       \
        UNPACK2(lo2, hi2, acc[i2][2]); UNPACK2(lo3, hi3, acc[i2][3]);       \
        long m0 = (rowBase) + (ty)*8 + i2*2;                                \
        if (m0 < (Mlim)) {                                                  \
            float4 v = make_float4(lo0 + bi.x, lo1 + bi.y,                  \
                                   lo2 + bi.z, lo3 + bi.w);                 \
            *(float4*)((dst) + m0 * (ldc) + (tx)*4) = v;                    \
        }                                                                   \
        if (m0 + 1 < (Mlim)) {                                              \
            float4 v = make_float4(hi0 + bi.x, hi1 + bi.y,                  \
                                   hi2 + bi.z, hi3 + bi.w);                 \
            *(float4*)((dst) + (m0 + 1) * (ldc) + (tx)*4) = v;              \
        }                                                                   \
    }

// ---------------------------------------------------------------------------
// GEMM 1: up-projection. M=81924, K=128, N=448 (7 col-tiles of 64).
// ---------------------------------------------------------------------------
__global__ __launch_bounds__(256) void gemm_up(
    const float* __restrict__ A, const float* __restrict__ W,
    const float* __restrict__ bias)
{
    __shared__ float As[64][128];
    __shared__ float Bs[64][64];
    const int  tid     = threadIdx.x;
    const long rowBase = (long)blockIdx.x * 128;
    const int  colBase = blockIdx.y * 64;
    const int  tx = tid & 15, ty = tid >> 4;

    unsigned long long acc[4][4];
#pragma unroll
    for (int i = 0; i < 4; i++)
#pragma unroll
        for (int j = 0; j < 4; j++) acc[i][j] = 0ULL;

    for (int kc = 0; kc < CIN / 64; kc++) {
#pragma unroll
        for (int it = 0; it < 8; it++) {
            int  idx = it * 256 + tid;
            int  r   = idx & 127;
            int  q   = idx >> 7;
            long m   = rowBase + r;
            float4 v = make_float4(0.f, 0.f, 0.f, 0.f);
            if (m < MUP)
                v = *(const float4*)(A + m * CIN + kc * 64 + q * 4);
            As[q*4+0][r] = v.x; As[q*4+1][r] = v.y;
            As[q*4+2][r] = v.z; As[q*4+3][r] = v.w;
        }
#pragma unroll
        for (int it = 0; it < 4; it++) {
            int idx = it * 256 + tid;
            int kr  = idx >> 4;
            int q   = idx & 15;
            *(float4*)&Bs[kr][q*4] =
                *(const float4*)(W + (long)(kc*64 + kr) * NUP + colBase + q*4);
        }
        __syncthreads();
        MICRO_KERNEL(As, Bs, acc, tx, ty)
        __syncthreads();
    }

    float4 bi = *(const float4*)(bias + colBase + tx*4);
    float* dst = g_h + colBase;
    EPILOGUE_STORE(dst, NUP, rowBase, MUP, bi, acc, tx, ty)
}

// ---------------------------------------------------------------------------
// Build x1_up
// ---------------------------------------------------------------------------
__global__ void build_xup(const int* __restrict__ topi, const int* __restrict__ downi)
{
    long idx = (long)blockIdx.x * blockDim.x + threadIdx.x;
    long total = (long)BB * NH * 16;
    if (idx >= total) return;
    long row = idx >> 4;
    int  q   = (int)(idx & 15);
    int  b   = (int)(row / NH);
    int  n   = (int)(row - (long)b * NH);
    const float* hb = g_h + (long)b * NR * 7 * CO;
    float4 v;
    if (n < NR) {
        int s = __ldg(topi + n);
        v = *(const float4*)(hb + (long)s * CO + q*4);
    } else {
        int m2 = n - NR;
        int s0 = __ldg(downi + 2*m2);
        int s1 = __ldg(downi + 2*m2 + 1);
        float4 a = *(const float4*)(hb + (long)s0 * CO + q*4);
        float4 c = *(const float4*)(hb + (long)s1 * CO + q*4);
        v = make_float4(0.5f*(a.x+c.x), 0.5f*(a.y+c.y),
                        0.5f*(a.z+c.z), 0.5f*(a.w+c.w));
    }
    *(float4*)(g_xup + row * CO + q*4) = v;
}

// ---------------------------------------------------------------------------
// GEMM 2: conv1, gathered A. K = 14 chunks of 64.
// ---------------------------------------------------------------------------
__global__ __launch_bounds__(256) void gemm_conv1(
    const float* __restrict__ x2, const int* __restrict__ neigh,
    const float* __restrict__ W, const float* __restrict__ bias)
{
    __shared__ float As[64][128];
    __shared__ float Bs[64][64];
    const int  tid     = threadIdx.x;
    const long rowBase = (long)blockIdx.x * 128;
    const int  tx = tid & 15, ty = tid >> 4;

    unsigned long long acc[4][4];
#pragma unroll
    for (int i = 0; i < 4; i++)
#pragma unroll
        for (int j = 0; j < 4; j++) acc[i][j] = 0ULL;

    for (int kc = 0; kc < 14; kc++) {
        const int j    = kc >> 1;
        const int half = kc & 1;
        const float* src = half ? x2 : g_xup;
#pragma unroll
        for (int it = 0; it < 8; it++) {
            int  idx = it * 256 + tid;
            int  r   = idx & 127;
            int  q   = idx >> 7;
            long m   = rowBase + r;
            float4 v = make_float4(0.f, 0.f, 0.f, 0.f);
            if (m < MC) {
                int b  = (int)(m / NH);
                int n  = (int)(m - (long)b * NH);
                int nb = __ldg(neigh + n*7 + j);
                v = *(const float4*)(src + ((long)b * NH + nb) * CO + q*4);
            }
            As[q*4+0][r] = v.x; As[q*4+1][r] = v.y;
            As[q*4+2][r] = v.z; As[q*4+3][r] = v.w;
        }
#pragma unroll
        for (int it = 0; it < 4; it++) {
            int idx = it * 256 + tid;
            int kr  = idx >> 4;
            int q   = idx & 15;
            *(float4*)&Bs[kr][q*4] =
                *(const float4*)(W + (long)(kc*64 + kr) * CO + q*4);
        }
        __syncthreads();
        MICRO_KERNEL(As, Bs, acc, tx, ty)
        __syncthreads();
    }

    float4 bi = *(const float4*)(bias + tx*4);
    EPILOGUE_STORE(g_y, CO, rowBase, MC, bi, acc, tx, ty)
}

// ---------------------------------------------------------------------------
// GEMM 3: conv2; BN1 + lrelu fused into gather load.
// ---------------------------------------------------------------------------
__global__ __launch_bounds__(256) void gemm_conv2(
    const int* __restrict__ neigh, const float* __restrict__ W,
    const float* __restrict__ bias, float* __restrict__ out)
{
    __shared__ float As[64][128];
    __shared__ float Bs[64][64];
    const int  tid     = threadIdx.x;
    const long rowBase = (long)blockIdx.x * 128;
    const int  tx = tid & 15, ty = tid >> 4;

    unsigned long long acc[4][4];
#pragma unroll
    for (int i = 0; i < 4; i++)
#pragma unroll
        for (int j = 0; j < 4; j++) acc[i][j] = 0ULL;

    for (int j = 0; j < 7; j++) {
#pragma unroll
        for (int it = 0; it < 8; it++) {
            int  idx = it * 256 + tid;
            int  r   = idx & 127;
            int  q   = idx >> 7;
            long m   = rowBase + r;
            float4 v = make_float4(0.f, 0.f, 0.f, 0.f);
            if (m < MC) {
                int b  = (int)(m / NH);
                int n  = (int)(m - (long)b * NH);
                int nb = __ldg(neigh + n*7 + j);
                v = *(const float4*)(g_y + ((long)b * NH + nb) * CO + q*4);
                float4 sc = *(const float4*)&g_bn[q*4];
                float4 sh = *(const float4*)&g_bn[64 + q*4];
                v.x = fmaf(v.x, sc.x, sh.x); v.x = v.x >= 0.f ? v.x : LRELU_SLOPE * v.x;
                v.y = fmaf(v.y, sc.y, sh.y); v.y = v.y >= 0.f ? v.y : LRELU_SLOPE * v.y;
                v.z = fmaf(v.z, sc.z, sh.z); v.z = v.z >= 0.f ? v.z : LRELU_SLOPE * v.z;
                v.w = fmaf(v.w, sc.w, sh.w); v.w = v.w >= 0.f ? v.w : LRELU_SLOPE * v.w;
            }
            As[q*4+0][r] = v.x; As[q*4+1][r] = v.y;
            As[q*4+2][r] = v.z; As[q*4+3][r] = v.w;
        }
#pragma unroll
        for (int it = 0; it < 4; it++) {
            int idx = it * 256 + tid;
            int kr  = idx >> 4;
            int q   = idx & 15;
            *(float4*)&Bs[kr][q*4] =
                *(const float4*)(W + (long)(j*64 + kr) * CO + q*4);
        }
        __syncthreads();
        MICRO_KERNEL(As, Bs, acc, tx, ty)
        __syncthreads();
    }

    float4 bi = *(const float4*)(bias + tx*4);
    EPILOGUE_STORE(out, CO, rowBase, MC, bi, acc, tx, ty)
}

// ---------------------------------------------------------------------------
// BN statistics: vectorized partials (float4 per thread), then finalize.
// ---------------------------------------------------------------------------
__global__ __launch_bounds__(256) void reduce_stats(const float* __restrict__ data, long Mrows)
{
    __shared__ float4 sh_s [16][16];
    __shared__ float4 sh_ss[16][16];
    int q  = threadIdx.x & 15;       // which float4 of the 64 channels
    int rg = threadIdx.x >> 4;       // 16 row groups
    float4 s  = make_float4(0.f, 0.f, 0.f, 0.f);
    float4 ss = make_float4(0.f, 0.f, 0.f, 0.f);
    for (long r = (long)blockIdx.x * 16 + rg; r < Mrows; r += (long)gridDim.x * 16) {
        float4 v = *(const float4*)(data + r * 64 + q * 4);
        s.x += v.x; s.y += v.y; s.z += v.z; s.w += v.w;
        ss.x = fmaf(v.x, v.x, ss.x); ss.y = fmaf(v.y, v.y, ss.y);
        ss.z = fmaf(v.z, v.z, ss.z); ss.w = fmaf(v.w, v.w, ss.w);
    }
    sh_s[rg][q] = s; sh_ss[rg][q] = ss;
    __syncthreads();
#pragma unroll
    for (int stride = 8; stride >= 1; stride >>= 1) {
        if (rg < stride) {
            float4 a = sh_s[rg][q],  b = sh_s[rg + stride][q];
            a.x += b.x; a.y += b.y; a.z += b.z; a.w += b.w;
            sh_s[rg][q] = a;
            float4 c = sh_ss[rg][q], d = sh_ss[rg + stride][q];
            c.x += d.x; c.y += d.y; c.z += d.z; c.w += d.w;
            sh_ss[rg][q] = c;
        }
        __syncthreads();
    }
    if (rg == 0) {
        *(float4*)(g_part + blockIdx.x * 128 + q*4)      = sh_s[0][q];
        *(float4*)(g_part + blockIdx.x * 128 + 64 + q*4) = sh_ss[0][q];
    }
}

__global__ void bn_finalize(const float* __restrict__ gamma,
                            const float* __restrict__ beta, float invM)
{
    int c = threadIdx.x;   // 0..63
    float s = 0.f, ss = 0.f;
    for (int p = 0; p < NPART; p++) {
        s  += g_part[p * 128 + c];
        ss += g_part[p * 128 + 64 + c];
    }
    float mean = s * invM;
    float var  = fmaf(-mean, mean, ss * invM);
    float sc   = gamma[c] * rsqrtf(var + BN_EPS);
    g_bn[c]      = sc;
    g_bn[64 + c] = beta[c] - mean * sc;
}

__global__ void apply_bn(float* __restrict__ out)
{
    long idx = (long)blockIdx.x * blockDim.x + threadIdx.x;
    if (idx >= MC * 16) return;
    int q = (int)(idx & 15);
    float4 v  = ((float4*)out)[idx];
    float4 sc = *(const float4*)&g_bn[q*4];
    float4 sh = *(const float4*)&g_bn[64 + q*4];
    v.x = fmaf(v.x, sc.x, sh.x); v.x = v.x >= 0.f ? v.x : LRELU_SLOPE * v.x;
    v.y = fmaf(v.y, sc.y, sh.y); v.y = v.y >= 0.f ? v.y : LRELU_SLOPE * v.y;
    v.z = fmaf(v.z, sc.z, sh.z); v.z = v.z >= 0.f ? v.z : LRELU_SLOPE * v.z;
    v.w = fmaf(v.w, sc.w, sh.w); v.w = v.w >= 0.f ? v.w : LRELU_SLOPE * v.w;
    ((float4*)out)[idx] = v;
}

// ---------------------------------------------------------------------------
extern "C" void kernel_launch(void* const* d_in, const int* in_sizes, int n_in,
                              void* d_out, int out_size)
{
    const float* x1    = (const float*)d_in[0];
    const float* x2    = (const float*)d_in[1];
    const int*   neigh = (const int*)  d_in[2];
    const int*   topi  = (const int*)  d_in[3];
    const int*   downi = (const int*)  d_in[4];
    const float* upW   = (const float*)d_in[5];
    const float* upb   = (const float*)d_in[6];
    const float* W1    = (const float*)d_in[7];
    const float* b1    = (const float*)d_in[8];
    const float* g1    = (const float*)d_in[9];
    const float* be1   = (const float*)d_in[10];
    const float* W2    = (const float*)d_in[11];
    const float* b2    = (const float*)d_in[12];
    const float* g2    = (const float*)d_in[13];
    const float* be2   = (const float*)d_in[14];
    float* out = (float*)d_out;

    void* yp = nullptr;
    cudaGetSymbolAddress(&yp, g_y);

    const int gemmBlocksUp = (int)((MUP + 127) / 128);
    const int gemmBlocksC  = (int)((MC  + 127) / 128);
    const long quads       = (long)BB * NH * 16;
    const int ewBlocks     = (int)((quads + 255) / 256);

    gemm_up   <<<dim3(gemmBlocksUp, 7), 256>>>(x1, upW, upb);
    build_xup <<<ewBlocks, 256>>>(topi, downi);
    gemm_conv1<<<gemmBlocksC, 256>>>(x2, neigh, W1, b1);
    reduce_stats<<<NPART, 256>>>((const float*)yp, MC);
    bn_finalize <<<1, 64>>>(g1, be1, 1.0f / (float)MC);
    gemm_conv2<<<gemmBlocksC, 256>>>(neigh, W2, b2, out);
    reduce_stats<<<NPART, 256>>>(out, MC);
    bn_finalize <<<1, 64>>>(g2, be2, 1.0f / (float)MC);
    apply_bn  <<<ewBlocks, 256>>>(out);
}

// round 4
// speedup vs baseline: 1.3400x; 1.2756x over previous
#include <cuda_runtime.h>
#include <cstdint>

#define LRELU_SLOPE 0.2f
#define BN_EPS 1e-5f

constexpr int  BB  = 2;
constexpr int  NR  = 40962;
constexpr int  NH  = 4 * NR - 6;      // 163842
constexpr int  CIN = 128;
constexpr int  CO  = 64;
constexpr int  NUP = 7 * CO;          // 448
constexpr long MUP = (long)BB * NR;   // 81924
constexpr long MC  = (long)BB * NH;   // 327684
constexpr int  NPART = 512;

__device__ float g_h   [(size_t)BB * NR * 7 * CO];
__device__ float g_xup [(size_t)BB * NH * CO];
__device__ float g_y   [(size_t)BB * NH * CO];
__device__ float g_part[NPART * 128];
__device__ float g_bn  [128];
// Fragment-ordered tf32 weights: [chunk][ks(8)][nt(8)][lane(32)][2]
__device__ float g_wupf[7 * 2 * 4096];   // up:   7 col-tiles x 2 k-chunks
__device__ float g_w1f [14 * 4096];      // conv1: 14 k-chunks
__device__ float g_w2f [7 * 4096];       // conv2: 7 k-chunks

#define TF32R(u, f) asm("cvt.rna.tf32.f32 %0, %1;" : "=r"(u) : "f"(f))

#define MMA_TF32(d, a0, a1, a2, a3, b0, b1)                                  \
    asm volatile("mma.sync.aligned.m16n8k8.row.col.f32.tf32.tf32.f32 "       \
        "{%0,%1,%2,%3}, {%4,%5,%6,%7}, {%8,%9}, {%0,%1,%2,%3};"              \
        : "+f"((d)[0]), "+f"((d)[1]), "+f"((d)[2]), "+f"((d)[3])             \
        : "r"(a0), "r"(a1), "r"(a2), "r"(a3), "r"(b0), "r"(b1))

constexpr int AS_STRIDE = 68;                    // floats; 68 % 32 == 4 -> conflict-free frag reads
constexpr int AS_FLOATS = 128 * AS_STRIDE;       // 8704
constexpr int BF_FLOATS = 4096;
constexpr int SMEM_DYN  = (AS_FLOATS + BF_FLOATS) * 4;   // 51,200 B

// Convert float4 -> tf32 bits, store as uint4
__device__ __forceinline__ void sts_tf32(float* dst, float4 v) {
    uint32_t w0, w1, w2, w3;
    TF32R(w0, v.x); TF32R(w1, v.y); TF32R(w2, v.z); TF32R(w3, v.w);
    uint4 u = make_uint4(w0, w1, w2, w3);
    *(uint4*)dst = u;
}

// ---------------------------------------------------------------------------
// Microkernel over one 64-k chunk + epilogue, shared by all three GEMMs
// ---------------------------------------------------------------------------
#define MK_COMPUTE()                                                          \
    {                                                                         \
        const int r0 = (warp << 4) + (lane >> 2);                             \
        const int c0 = lane & 3;                                              \
        _Pragma("unroll")                                                     \
        for (int ks = 0; ks < 8; ks++) {                                      \
            uint32_t a0 = __float_as_uint(As[ r0      * AS_STRIDE + ks*8 + c0    ]); \
            uint32_t a1 = __float_as_uint(As[(r0 + 8) * AS_STRIDE + ks*8 + c0    ]); \
            uint32_t a2 = __float_as_uint(As[ r0      * AS_STRIDE + ks*8 + c0 + 4]); \
            uint32_t a3 = __float_as_uint(As[(r0 + 8) * AS_STRIDE + ks*8 + c0 + 4]); \
            _Pragma("unroll")                                                 \
            for (int nt = 0; nt < 8; nt++) {                                  \
                float2 b = *(const float2*)&Bf[(((ks << 3) + nt) * 32 + lane) * 2]; \
                MMA_TF32(acc[nt], a0, a1, a2, a3,                             \
                         __float_as_uint(b.x), __float_as_uint(b.y));         \
            }                                                                 \
        }                                                                     \
    }

#define MK_BFILL(gsrc)                                                        \
    {                                                                         \
        const float4* wsrc = (const float4*)(gsrc) + tid;                     \
        float4* wdst = (float4*)Bf + tid;                                     \
        _Pragma("unroll")                                                     \
        for (int i = 0; i < 4; i++) wdst[i * 256] = wsrc[i * 256];            \
    }

#define MK_EPILOGUE(dst, ldc, Mlim, biasp)                                    \
    {                                                                         \
        long mr = rowBase + (warp << 4) + (lane >> 2);                        \
        int  cb = (lane & 3) * 2;                                             \
        _Pragma("unroll")                                                     \
        for (int nt = 0; nt < 8; nt++) {                                      \
            float bx = (biasp)[nt * 8 + cb];                                  \
            float by = (biasp)[nt * 8 + cb + 1];                              \
            if (mr < (Mlim)) {                                                \
                float2 v = make_float2(acc[nt][0] + bx, acc[nt][1] + by);     \
                *(float2*)((dst) + mr * (ldc) + nt * 8 + cb) = v;             \
            }                                                                 \
            if (mr + 8 < (Mlim)) {                                            \
                float2 v = make_float2(acc[nt][2] + bx, acc[nt][3] + by);     \
                *(float2*)((dst) + (mr + 8) * (ldc) + nt * 8 + cb) = v;       \
            }                                                                 \
        }                                                                     \
    }

// ---------------------------------------------------------------------------
// Weight prep: transpose + tf32 round + fragment ordering
// ---------------------------------------------------------------------------
__global__ void prep_weights(const float* __restrict__ upW,
                             const float* __restrict__ W1,
                             const float* __restrict__ W2)
{
    int f = blockIdx.x * 256 + threadIdx.x;
    if (f >= 143360) return;
    int which, rel, t = 0;
    if (f < 57344)       { which = 0; rel = f; t = rel >> 13; rel &= 8191; }
    else if (f < 114688) { which = 1; rel = f - 57344; }
    else                 { which = 2; rel = f - 114688; }
    int kc = rel >> 12;
    int c  = rel & 4095;
    int entry = c >> 1, i = c & 1;
    int ks = entry >> 8, nt = (entry >> 5) & 7, lane = entry & 31;
    int nloc = nt * 8 + (lane >> 2);
    int k    = kc * 64 + ks * 8 + (lane & 3) + 4 * i;
    float src;
    if (which == 0)      src = upW[k * 448 + t * 64 + nloc];
    else if (which == 1) src = W1[k * 64 + nloc];
    else                 src = W2[k * 64 + nloc];
    uint32_t u; TF32R(u, src);
    if (which == 0)      g_wupf[f]          = __uint_as_float(u);
    else if (which == 1) g_w1f[f - 57344]   = __uint_as_float(u);
    else                 g_w2f[f - 114688]  = __uint_as_float(u);
}

// ---------------------------------------------------------------------------
// GEMM 1: up-projection.  grid (ceil(MUP/128), 7)
// ---------------------------------------------------------------------------
__global__ __launch_bounds__(256) void gemm_up_mma(
    const float* __restrict__ x1, const float* __restrict__ bias)
{
    extern __shared__ float sm[];
    float* As = sm;
    float* Bf = sm + AS_FLOATS;
    const int tid = threadIdx.x, lane = tid & 31, warp = tid >> 5;
    const long rowBase = (long)blockIdx.x * 128;
    const int  tcol    = blockIdx.y;           // 64-col tile

    const int fr = tid & 127, fh = tid >> 7;
    long fm = rowBase + fr; if (fm >= MUP) fm = MUP - 1;
    const float4* arow = (const float4*)(x1 + fm * CIN + fh * 32);

    float acc[8][4];
#pragma unroll
    for (int i = 0; i < 8; i++)
#pragma unroll
        for (int j = 0; j < 4; j++) acc[i][j] = 0.f;

    for (int kc = 0; kc < 2; kc++) {
        __syncthreads();
#pragma unroll
        for (int i = 0; i < 8; i++)
            sts_tf32(&As[fr * AS_STRIDE + fh * 32 + i * 4], arow[kc * 16 + i]);
        MK_BFILL(g_wupf + (tcol * 2 + kc) * 4096);
        __syncthreads();
        MK_COMPUTE();
    }
    MK_EPILOGUE(g_h + tcol * 64, NUP, MUP, bias + tcol * 64);
}

// ---------------------------------------------------------------------------
// Build x1_up
// ---------------------------------------------------------------------------
__global__ void build_xup(const int* __restrict__ topi, const int* __restrict__ downi)
{
    long idx = (long)blockIdx.x * blockDim.x + threadIdx.x;
    long total = (long)BB * NH * 16;
    if (idx >= total) return;
    long row = idx >> 4;
    int  q = (int)(idx & 15);
    int  b = (int)(row / NH);
    int  n = (int)(row - (long)b * NH);
    const float* hb = g_h + (long)b * NR * 7 * CO;
    float4 v;
    if (n < NR) {
        int s = __ldg(topi + n);
        v = *(const float4*)(hb + (long)s * CO + q * 4);
    } else {
        int m2 = n - NR;
        int s0 = __ldg(downi + 2 * m2);
        int s1 = __ldg(downi + 2 * m2 + 1);
        float4 a = *(const float4*)(hb + (long)s0 * CO + q * 4);
        float4 c = *(const float4*)(hb + (long)s1 * CO + q * 4);
        v = make_float4(0.5f * (a.x + c.x), 0.5f * (a.y + c.y),
                        0.5f * (a.z + c.z), 0.5f * (a.w + c.w));
    }
    *(float4*)(g_xup + row * CO + q * 4) = v;
}

// ---------------------------------------------------------------------------
// GEMM 2: conv1 (gathered A). 14 k-chunks of 64.
// ---------------------------------------------------------------------------
__global__ __launch_bounds__(256) void gemm_conv1_mma(
    const float* __restrict__ x2, const int* __restrict__ neigh,
    const float* __restrict__ bias)
{
    extern __shared__ float sm[];
    float* As = sm;
    float* Bf = sm + AS_FLOATS;
    const int tid = threadIdx.x, lane = tid & 31, warp = tid >> 5;
    const long rowBase = (long)blockIdx.x * 128;

    const int fr = tid & 127, fh = tid >> 7;
    long fm = rowBase + fr; if (fm >= MC) fm = MC - 1;
    const int fb = (int)(fm / NH);
    const int fn = (int)(fm - (long)fb * NH);
    const int* nrow = neigh + (long)fn * 7;
    const long bbase = (long)fb * NH;

    float acc[8][4];
#pragma unroll
    for (int i = 0; i < 8; i++)
#pragma unroll
        for (int j = 0; j < 4; j++) acc[i][j] = 0.f;

    for (int kc = 0; kc < 14; kc++) {
        const int j = kc >> 1, half = kc & 1;
        const float* src = half ? x2 : g_xup;
        int nb = __ldg(nrow + j);
        const float4* sp = (const float4*)(src + (bbase + nb) * CO + fh * 32);
        __syncthreads();
#pragma unroll
        for (int i = 0; i < 8; i++)
            sts_tf32(&As[fr * AS_STRIDE + fh * 32 + i * 4], sp[i]);
        MK_BFILL(g_w1f + kc * 4096);
        __syncthreads();
        MK_COMPUTE();
    }
    MK_EPILOGUE(g_y, CO, MC, bias);
}

// ---------------------------------------------------------------------------
// GEMM 3: conv2; BN1 + lrelu fused into the gather. 7 k-chunks of 64.
// ---------------------------------------------------------------------------
__global__ __launch_bounds__(256) void gemm_conv2_mma(
    const int* __restrict__ neigh, const float* __restrict__ bias,
    float* __restrict__ out)
{
    extern __shared__ float sm[];
    float* As = sm;
    float* Bf = sm + AS_FLOATS;
    const int tid = threadIdx.x, lane = tid & 31, warp = tid >> 5;
    const long rowBase = (long)blockIdx.x * 128;

    const int fr = tid & 127, fh = tid >> 7;
    long fm = rowBase + fr; if (fm >= MC) fm = MC - 1;
    const int fb = (int)(fm / NH);
    const int fn = (int)(fm - (long)fb * NH);
    const int* nrow = neigh + (long)fn * 7;
    const long bbase = (long)fb * NH;

    float acc[8][4];
#pragma unroll
    for (int i = 0; i < 8; i++)
#pragma unroll
        for (int j = 0; j < 4; j++) acc[i][j] = 0.f;

    for (int kc = 0; kc < 7; kc++) {
        int nb = __ldg(nrow + kc);
        const float4* sp = (const float4*)(g_y + (bbase + nb) * CO + fh * 32);
        __syncthreads();
#pragma unroll
        for (int i = 0; i < 8; i++) {
            float4 v  = sp[i];
            float4 sc = *(const float4*)&g_bn[fh * 32 + i * 4];
            float4 sh = *(const float4*)&g_bn[64 + fh * 32 + i * 4];
            v.x = fmaf(v.x, sc.x, sh.x); v.x = v.x >= 0.f ? v.x : LRELU_SLOPE * v.x;
            v.y = fmaf(v.y, sc.y, sh.y); v.y = v.y >= 0.f ? v.y : LRELU_SLOPE * v.y;
            v.z = fmaf(v.z, sc.z, sh.z); v.z = v.z >= 0.f ? v.z : LRELU_SLOPE * v.z;
            v.w = fmaf(v.w, sc.w, sh.w); v.w = v.w >= 0.f ? v.w : LRELU_SLOPE * v.w;
            sts_tf32(&As[fr * AS_STRIDE + fh * 32 + i * 4], v);
        }
        MK_BFILL(g_w2f + kc * 4096);
        __syncthreads();
        MK_COMPUTE();
    }
    MK_EPILOGUE(out, CO, MC, bias);
}

// ---------------------------------------------------------------------------
// BN statistics + finalize + final elementwise BN
// ---------------------------------------------------------------------------
__global__ __launch_bounds__(256) void reduce_stats(const float* __restrict__ data, long Mrows)
{
    __shared__ float4 sh_s [16][16];
    __shared__ float4 sh_ss[16][16];
    int q  = threadIdx.x & 15;
    int rg = threadIdx.x >> 4;
    float4 s  = make_float4(0.f, 0.f, 0.f, 0.f);
    float4 ss = make_float4(0.f, 0.f, 0.f, 0.f);
    for (long r = (long)blockIdx.x * 16 + rg; r < Mrows; r += (long)gridDim.x * 16) {
        float4 v = *(const float4*)(data + r * 64 + q * 4);
        s.x += v.x; s.y += v.y; s.z += v.z; s.w += v.w;
        ss.x = fmaf(v.x, v.x, ss.x); ss.y = fmaf(v.y, v.y, ss.y);
        ss.z = fmaf(v.z, v.z, ss.z); ss.w = fmaf(v.w, v.w, ss.w);
    }
    sh_s[rg][q] = s; sh_ss[rg][q] = ss;
    __syncthreads();
#pragma unroll
    for (int stride = 8; stride >= 1; stride >>= 1) {
        if (rg < stride) {
            float4 a = sh_s[rg][q], b = sh_s[rg + stride][q];
            a.x += b.x; a.y += b.y; a.z += b.z; a.w += b.w;
            sh_s[rg][q] = a;
            float4 c = sh_ss[rg][q], d = sh_ss[rg + stride][q];
            c.x += d.x; c.y += d.y; c.z += d.z; c.w += d.w;
            sh_ss[rg][q] = c;
        }
        __syncthreads();
    }
    if (rg == 0) {
        *(float4*)(g_part + blockIdx.x * 128 + q * 4)      = sh_s[0][q];
        *(float4*)(g_part + blockIdx.x * 128 + 64 + q * 4) = sh_ss[0][q];
    }
}

__global__ void bn_finalize(const float* __restrict__ gamma,
                            const float* __restrict__ beta, float invM)
{
    int c = threadIdx.x;
    float s = 0.f, ss = 0.f;
    for (int p = 0; p < NPART; p++) {
        s  += g_part[p * 128 + c];
        ss += g_part[p * 128 + 64 + c];
    }
    float mean = s * invM;
    float var  = fmaf(-mean, mean, ss * invM);
    float sc   = gamma[c] * rsqrtf(var + BN_EPS);
    g_bn[c]      = sc;
    g_bn[64 + c] = beta[c] - mean * sc;
}

__global__ void apply_bn(float* __restrict__ out)
{
    long idx = (long)blockIdx.x * blockDim.x + threadIdx.x;
    if (idx >= MC * 16) return;
    int q = (int)(idx & 15);
    float4 v  = ((float4*)out)[idx];
    float4 sc = *(const float4*)&g_bn[q * 4];
    float4 sh = *(const float4*)&g_bn[64 + q * 4];
    v.x = fmaf(v.x, sc.x, sh.x); v.x = v.x >= 0.f ? v.x : LRELU_SLOPE * v.x;
    v.y = fmaf(v.y, sc.y, sh.y); v.y = v.y >= 0.f ? v.y : LRELU_SLOPE * v.y;
    v.z = fmaf(v.z, sc.z, sh.z); v.z = v.z >= 0.f ? v.z : LRELU_SLOPE * v.z;
    v.w = fmaf(v.w, sc.w, sh.w); v.w = v.w >= 0.f ? v.w : LRELU_SLOPE * v.w;
    ((float4*)out)[idx] = v;
}

// ---------------------------------------------------------------------------
extern "C" void kernel_launch(void* const* d_in, const int* in_sizes, int n_in,
                              void* d_out, int out_size)
{
    const float* x1    = (const float*)d_in[0];
    const float* x2    = (const float*)d_in[1];
    const int*   neigh = (const int*)  d_in[2];
    const int*   topi  = (const int*)  d_in[3];
    const int*   downi = (const int*)  d_in[4];
    const float* upW   = (const float*)d_in[5];
    const float* upb   = (const float*)d_in[6];
    const float* W1    = (const float*)d_in[7];
    const float* b1    = (const float*)d_in[8];
    const float* g1    = (const float*)d_in[9];
    const float* be1   = (const float*)d_in[10];
    const float* W2    = (const float*)d_in[11];
    const float* b2    = (const float*)d_in[12];
    const float* g2    = (const float*)d_in[13];
    const float* be2   = (const float*)d_in[14];
    float* out = (float*)d_out;

    static bool attr_set = false;
    if (!attr_set) {
        cudaFuncSetAttribute(gemm_up_mma,    cudaFuncAttributeMaxDynamicSharedMemorySize, SMEM_DYN);
        cudaFuncSetAttribute(gemm_conv1_mma, cudaFuncAttributeMaxDynamicSharedMemorySize, SMEM_DYN);
        cudaFuncSetAttribute(gemm_conv2_mma, cudaFuncAttributeMaxDynamicSharedMemorySize, SMEM_DYN);
        attr_set = true;
    }

    void* yp = nullptr;
    cudaGetSymbolAddress(&yp, g_y);

    const int blkUp = (int)((MUP + 127) / 128);
    const int blkC  = (int)((MC  + 127) / 128);
    const long quads = (long)BB * NH * 16;
    const int ewBlocks = (int)((quads + 255) / 256);
    const int pwBlocks = (143360 + 255) / 256;

    prep_weights  <<<pwBlocks, 256>>>(upW, W1, W2);
    gemm_up_mma   <<<dim3(blkUp, 7), 256, SMEM_DYN>>>(x1, upb);
    build_xup     <<<ewBlocks, 256>>>(topi, downi);
    gemm_conv1_mma<<<blkC, 256, SMEM_DYN>>>(x2, neigh, b1);
    reduce_stats  <<<NPART, 256>>>((const float*)yp, MC);
    bn_finalize   <<<1, 64>>>(g1, be1, 1.0f / (float)MC);
    gemm_conv2_mma<<<blkC, 256, SMEM_DYN>>>(neigh, b2, out);
    reduce_stats  <<<NPART, 256>>>(out, MC);
    bn_finalize   <<<1, 64>>>(g2, be2, 1.0f / (float)MC);
    apply_bn      <<<ewBlocks, 256>>>(out);
}

// round 5
// speedup vs baseline: 1.7412x; 1.2994x over previous
#include <cuda_runtime.h>
#include <cstdint>

#define LRELU_SLOPE 0.2f
#define BN_EPS 1e-5f

constexpr int  BB  = 2;
constexpr int  NR  = 40962;
constexpr int  NH  = 4 * NR - 6;      // 163842
constexpr int  CIN = 128;
constexpr int  CO  = 64;
constexpr int  NUP = 7 * CO;          // 448
constexpr long MUP = (long)BB * NR;   // 81924
constexpr long MC  = (long)BB * NH;   // 327684
constexpr int  NPART = 512;

__device__ float g_h   [(size_t)BB * NR * 7 * CO];   // up output, fp32
__device__ float g_xup [(size_t)BB * NH * CO];       // x1_up, tf32-rounded
__device__ float g_y   [(size_t)BB * NH * CO];       // conv1 out fp32 -> bn1+round in place
__device__ float g_x1t [(size_t)BB * NR * CIN];      // x1 tf32-rounded
__device__ float g_x2t [(size_t)BB * NH * CO];       // x2 tf32-rounded
__device__ float g_part[NPART * 128];
__device__ float g_bn  [128];
// Fragment-packed tf32 weights: per chunk 4096 floats,
// float4 unit index (ks*4+np)*32 + lane; unit = {nt=2np:(i0,i1), nt=2np+1:(i0,i1)}
__device__ float g_wupf[7 * 2 * 4096];
__device__ float g_w1f [14 * 4096];
__device__ float g_w2f [7 * 4096];

#define TF32R(u, f) asm("cvt.rna.tf32.f32 %0, %1;" : "=r"(u) : "f"(f))

#define MMA_TF32(d, a0, a1, a2, a3, b0, b1)                                  \
    asm volatile("mma.sync.aligned.m16n8k8.row.col.f32.tf32.tf32.f32 "       \
        "{%0,%1,%2,%3}, {%4,%5,%6,%7}, {%8,%9}, {%0,%1,%2,%3};"              \
        : "+f"((d)[0]), "+f"((d)[1]), "+f"((d)[2]), "+f"((d)[3])             \
        : "r"(a0), "r"(a1), "r"(a2), "r"(a3), "r"(b0), "r"(b1))

#define CP_ASYNC16(dst_u32, src)                                             \
    asm volatile("cp.async.cg.shared.global [%0], [%1], 16;"                 \
                 :: "r"(dst_u32), "l"(src) : "memory")
#define CP_COMMIT()  asm volatile("cp.async.commit_group;" ::: "memory")
#define CP_WAIT(n)   asm volatile("cp.async.wait_group %0;" :: "n"(n) : "memory")

constexpr int AS_STRIDE = 68;                 // 68 % 32 == 4 -> conflict-free frag reads
constexpr int AS_FLOATS = 128 * AS_STRIDE;    // per buffer
constexpr int SMEM_DYN  = 2 * AS_FLOATS * 4;  // 69,632 B

// ---------------------------------------------------------------------------
// Round a float buffer to tf32 (vectorized)
// ---------------------------------------------------------------------------
__global__ void round_tf32(const float* __restrict__ src, float* __restrict__ dst, long nquads)
{
    long i = (long)blockIdx.x * blockDim.x + threadIdx.x;
    if (i >= nquads) return;
    float4 v = ((const float4*)src)[i];
    uint32_t a, b, c, d;
    TF32R(a, v.x); TF32R(b, v.y); TF32R(c, v.z); TF32R(d, v.w);
    ((uint4*)dst)[i] = make_uint4(a, b, c, d);
}

// ---------------------------------------------------------------------------
// Weight prep: transpose + tf32 round + fragment packing
// ---------------------------------------------------------------------------
__global__ void prep_weights(const float* __restrict__ upW,
                             const float* __restrict__ W1,
                             const float* __restrict__ W2)
{
    int f = blockIdx.x * 256 + threadIdx.x;
    if (f >= 143360) return;
    int which, rel, t = 0;
    if (f < 57344)       { which = 0; rel = f; t = rel >> 13; rel &= 8191; }
    else if (f < 114688) { which = 1; rel = f - 57344; }
    else                 { which = 2; rel = f - 114688; }
    int kc = rel >> 12;
    int c  = rel & 4095;
    // float4-packed: c = (((ks*4+np)*32)+lane)*4 + q
    int q    = c & 3;
    int lane = (c >> 2) & 31;
    int np   = (c >> 7) & 3;
    int ks   = (c >> 9) & 7;
    int nt   = np * 2 + (q >> 1);
    int i    = q & 1;
    int nloc = nt * 8 + (lane >> 2);
    int k    = kc * 64 + ks * 8 + (lane & 3) + 4 * i;
    float src;
    if (which == 0)      src = upW[k * 448 + t * 64 + nloc];
    else if (which == 1) src = W1[k * 64 + nloc];
    else                 src = W2[k * 64 + nloc];
    uint32_t u; TF32R(u, src);
    if (which == 0)      g_wupf[f]         = __uint_as_float(u);
    else if (which == 1) g_w1f[f - 57344]  = __uint_as_float(u);
    else                 g_w2f[f - 114688] = __uint_as_float(u);
}

// ---------------------------------------------------------------------------
// Common GEMM machinery
// ---------------------------------------------------------------------------
#define MK_VARS()                                                             \
    extern __shared__ float sm[];                                             \
    const int tid = threadIdx.x, lane = tid & 31, warp = tid >> 5;            \
    const int fr = tid & 127, fh = tid >> 7;                                  \
    uint32_t as_u32 = (uint32_t)__cvta_generic_to_shared(sm);                 \
    float acc[8][4];                                                          \
    _Pragma("unroll") for (int i = 0; i < 8; i++)                             \
    _Pragma("unroll") for (int j = 0; j < 4; j++) acc[i][j] = 0.f;

// Issue 8x16B cp.async for this thread's half-row into buffer `buf`
#define MK_ISSUE(buf, rowptr)                                                 \
    {                                                                         \
        uint32_t d = as_u32 + ((buf) * AS_FLOATS + fr * AS_STRIDE + fh * 32) * 4; \
        const float4* s = (const float4*)(rowptr) + fh * 8;                   \
        _Pragma("unroll")                                                     \
        for (int i = 0; i < 8; i++) CP_ASYNC16(d + i * 16, s + i);            \
        CP_COMMIT();                                                          \
    }

#define MK_COMPUTE(buf, bchunk)                                               \
    {                                                                         \
        const float* As = sm + (buf) * AS_FLOATS;                             \
        const float4* bp = (const float4*)(bchunk);                           \
        const int r0 = (warp << 4) + (lane >> 2);                             \
        const int c0 = lane & 3;                                              \
        _Pragma("unroll")                                                     \
        for (int ks = 0; ks < 8; ks++) {                                      \
            uint32_t a0 = __float_as_uint(As[ r0      * AS_STRIDE + ks*8 + c0    ]); \
            uint32_t a1 = __float_as_uint(As[(r0 + 8) * AS_STRIDE + ks*8 + c0    ]); \
            uint32_t a2 = __float_as_uint(As[ r0      * AS_STRIDE + ks*8 + c0 + 4]); \
            uint32_t a3 = __float_as_uint(As[(r0 + 8) * AS_STRIDE + ks*8 + c0 + 4]); \
            _Pragma("unroll")                                                 \
            for (int np = 0; np < 4; np++) {                                  \
                float4 bv = __ldg(bp + (ks * 4 + np) * 32 + lane);            \
                MMA_TF32(acc[np*2],   a0, a1, a2, a3,                         \
                         __float_as_uint(bv.x), __float_as_uint(bv.y));       \
                MMA_TF32(acc[np*2+1], a0, a1, a2, a3,                         \
                         __float_as_uint(bv.z), __float_as_uint(bv.w));       \
            }                                                                 \
        }                                                                     \
    }

#define MK_EPILOGUE(dst, ldc, Mlim, biasp)                                    \
    {                                                                         \
        long mr = rowBase + (warp << 4) + (lane >> 2);                        \
        int  cb = (lane & 3) * 2;                                             \
        _Pragma("unroll")                                                     \
        for (int nt = 0; nt < 8; nt++) {                                      \
            float bx = (biasp)[nt * 8 + cb];                                  \
            float by = (biasp)[nt * 8 + cb + 1];                              \
            if (mr < (Mlim)) {                                                \
                float2 v = make_float2(acc[nt][0] + bx, acc[nt][1] + by);     \
                *(float2*)((dst) + mr * (ldc) + nt * 8 + cb) = v;             \
            }                                                                 \
            if (mr + 8 < (Mlim)) {                                            \
                float2 v = make_float2(acc[nt][2] + bx, acc[nt][3] + by);     \
                *(float2*)((dst) + (mr + 8) * (ldc) + nt * 8 + cb) = v;       \
            }                                                                 \
        }                                                                     \
    }

// ---------------------------------------------------------------------------
// GEMM 1: up-projection. grid (ceil(MUP/128), 7). A = g_x1t (tf32).
// ---------------------------------------------------------------------------
__global__ __launch_bounds__(256) void gemm_up_mma(const float* __restrict__ bias)
{
    MK_VARS();
    const long rowBase = (long)blockIdx.x * 128;
    const int  tcol    = blockIdx.y;
    long fm = rowBase + fr; if (fm >= MUP) fm = MUP - 1;
    const float* arow = g_x1t + fm * CIN;
    const float* bw   = g_wupf + tcol * 2 * 4096;

    MK_ISSUE(0, arow);
    for (int kc = 0; kc < 2; kc++) {
        if (kc < 1) { MK_ISSUE(1, arow + 64); CP_WAIT(1); }
        else CP_WAIT(0);
        __syncthreads();
        MK_COMPUTE(kc & 1, bw + kc * 4096);
        __syncthreads();
    }
    MK_EPILOGUE(g_h + tcol * 64, NUP, MUP, bias + tcol * 64);
}

// ---------------------------------------------------------------------------
// Build x1_up (writes tf32-rounded)
// ---------------------------------------------------------------------------
__global__ void build_xup(const int* __restrict__ topi, const int* __restrict__ downi)
{
    long idx = (long)blockIdx.x * blockDim.x + threadIdx.x;
    long total = (long)BB * NH * 16;
    if (idx >= total) return;
    long row = idx >> 4;
    int  q = (int)(idx & 15);
    int  b = (int)(row / NH);
    int  n = (int)(row - (long)b * NH);
    const float* hb = g_h + (long)b * NR * 7 * CO;
    float4 v;
    if (n < NR) {
        int s = __ldg(topi + n);
        v = *(const float4*)(hb + (long)s * CO + q * 4);
    } else {
        int m2 = n - NR;
        int s0 = __ldg(downi + 2 * m2);
        int s1 = __ldg(downi + 2 * m2 + 1);
        float4 a = *(const float4*)(hb + (long)s0 * CO + q * 4);
        float4 c = *(const float4*)(hb + (long)s1 * CO + q * 4);
        v = make_float4(0.5f * (a.x + c.x), 0.5f * (a.y + c.y),
                        0.5f * (a.z + c.z), 0.5f * (a.w + c.w));
    }
    uint32_t a_, b_, c_, d_;
    TF32R(a_, v.x); TF32R(b_, v.y); TF32R(c_, v.z); TF32R(d_, v.w);
    *(uint4*)(g_xup + row * CO + q * 4) = make_uint4(a_, b_, c_, d_);
}

// ---------------------------------------------------------------------------
// GEMM 2: conv1 (gathered A from g_xup / g_x2t, both tf32). 14 chunks.
// ---------------------------------------------------------------------------
__global__ __launch_bounds__(256) void gemm_conv1_mma(const float* __restrict__ bias,
                                                      const int* __restrict__ neigh)
{
    MK_VARS();
    const long rowBase = (long)blockIdx.x * 128;
    long fm = rowBase + fr; if (fm >= MC) fm = MC - 1;
    const int  fb = (int)(fm / NH);
    const int  fn = (int)(fm - (long)fb * NH);
    const long bbase = (long)fb * NH;
    int nidx[7];
#pragma unroll
    for (int j = 0; j < 7; j++) nidx[j] = __ldg(neigh + (long)fn * 7 + j);

#define C1_ROW(kc) (((kc) & 1 ? g_x2t : g_xup) + (bbase + nidx[(kc) >> 1]) * CO)
    MK_ISSUE(0, C1_ROW(0));
    for (int kc = 0; kc < 14; kc++) {
        if (kc < 13) { MK_ISSUE((kc + 1) & 1, C1_ROW(kc + 1)); CP_WAIT(1); }
        else CP_WAIT(0);
        __syncthreads();
        MK_COMPUTE(kc & 1, g_w1f + kc * 4096);
        __syncthreads();
    }
#undef C1_ROW
    MK_EPILOGUE(g_y, CO, MC, bias);
}

// ---------------------------------------------------------------------------
// GEMM 3: conv2 (gathered A from g_y, already bn1+lrelu+tf32). 7 chunks.
// ---------------------------------------------------------------------------
__global__ __launch_bounds__(256) void gemm_conv2_mma(const float* __restrict__ bias,
                                                      const int* __restrict__ neigh,
                                                      float* __restrict__ out)
{
    MK_VARS();
    const long rowBase = (long)blockIdx.x * 128;
    long fm = rowBase + fr; if (fm >= MC) fm = MC - 1;
    const int  fb = (int)(fm / NH);
    const int  fn = (int)(fm - (long)fb * NH);
    const long bbase = (long)fb * NH;
    int nidx[7];
#pragma unroll
    for (int j = 0; j < 7; j++) nidx[j] = __ldg(neigh + (long)fn * 7 + j);

    MK_ISSUE(0, g_y + (bbase + nidx[0]) * CO);
    for (int kc = 0; kc < 7; kc++) {
        if (kc < 6) { MK_ISSUE((kc + 1) & 1, g_y + (bbase + nidx[kc + 1]) * CO); CP_WAIT(1); }
        else CP_WAIT(0);
        __syncthreads();
        MK_COMPUTE(kc & 1, g_w2f + kc * 4096);
        __syncthreads();
    }
    MK_EPILOGUE(out, CO, MC, bias);
}

// ---------------------------------------------------------------------------
// BN statistics / finalize / elementwise
// ---------------------------------------------------------------------------
__global__ __launch_bounds__(256) void reduce_stats(const float* __restrict__ data, long Mrows)
{
    __shared__ float4 sh_s [16][16];
    __shared__ float4 sh_ss[16][16];
    int q  = threadIdx.x & 15;
    int rg = threadIdx.x >> 4;
    float4 s  = make_float4(0.f, 0.f, 0.f, 0.f);
    float4 ss = make_float4(0.f, 0.f, 0.f, 0.f);
    for (long r = (long)blockIdx.x * 16 + rg; r < Mrows; r += (long)gridDim.x * 16) {
        float4 v = *(const float4*)(data + r * 64 + q * 4);
        s.x += v.x; s.y += v.y; s.z += v.z; s.w += v.w;
        ss.x = fmaf(v.x, v.x, ss.x); ss.y = fmaf(v.y, v.y, ss.y);
        ss.z = fmaf(v.z, v.z, ss.z); ss.w = fmaf(v.w, v.w, ss.w);
    }
    sh_s[rg][q] = s; sh_ss[rg][q] = ss;
    __syncthreads();
#pragma unroll
    for (int stride = 8; stride >= 1; stride >>= 1) {
        if (rg < stride) {
            float4 a = sh_s[rg][q], b = sh_s[rg + stride][q];
            a.x += b.x; a.y += b.y; a.z += b.z; a.w += b.w;
            sh_s[rg][q] = a;
            float4 c = sh_ss[rg][q], d = sh_ss[rg + stride][q];
            c.x += d.x; c.y += d.y; c.z += d.z; c.w += d.w;
            sh_ss[rg][q] = c;
        }
        __syncthreads();
    }
    if (rg == 0) {
        *(float4*)(g_part + blockIdx.x * 128 + q * 4)      = sh_s[0][q];
        *(float4*)(g_part + blockIdx.x * 128 + 64 + q * 4) = sh_ss[0][q];
    }
}

__global__ void bn_finalize(const float* __restrict__ gamma,
                            const float* __restrict__ beta, float invM)
{
    int c = threadIdx.x;
    float s = 0.f, ss = 0.f;
    for (int p = 0; p < NPART; p++) {
        s  += g_part[p * 128 + c];
        ss += g_part[p * 128 + 64 + c];
    }
    float mean = s * invM;
    float var  = fmaf(-mean, mean, ss * invM);
    float sc   = gamma[c] * rsqrtf(var + BN_EPS);
    g_bn[c]      = sc;
    g_bn[64 + c] = beta[c] - mean * sc;
}

// BN1 + lrelu + tf32 round, in place on g_y
__global__ void apply_bn1_round()
{
    long idx = (long)blockIdx.x * blockDim.x + threadIdx.x;
    if (idx >= MC * 16) return;
    int q = (int)(idx & 15);
    float4 v  = ((float4*)g_y)[idx];
    float4 sc = *(const float4*)&g_bn[q * 4];
    float4 sh = *(const float4*)&g_bn[64 + q * 4];
    v.x = fmaf(v.x, sc.x, sh.x); v.x = v.x >= 0.f ? v.x : LRELU_SLOPE * v.x;
    v.y = fmaf(v.y, sc.y, sh.y); v.y = v.y >= 0.f ? v.y : LRELU_SLOPE * v.y;
    v.z = fmaf(v.z, sc.z, sh.z); v.z = v.z >= 0.f ? v.z : LRELU_SLOPE * v.z;
    v.w = fmaf(v.w, sc.w, sh.w); v.w = v.w >= 0.f ? v.w : LRELU_SLOPE * v.w;
    uint32_t a, b, c, d;
    TF32R(a, v.x); TF32R(b, v.y); TF32R(c, v.z); TF32R(d, v.w);
    ((uint4*)g_y)[idx] = make_uint4(a, b, c, d);
}

__global__ void apply_bn(float* __restrict__ out)
{
    long idx = (long)blockIdx.x * blockDim.x + threadIdx.x;
    if (idx >= MC * 16) return;
    int q = (int)(idx & 15);
    float4 v  = ((float4*)out)[idx];
    float4 sc = *(const float4*)&g_bn[q * 4];
    float4 sh = *(const float4*)&g_bn[64 + q * 4];
    v.x = fmaf(v.x, sc.x, sh.x); v.x = v.x >= 0.f ? v.x : LRELU_SLOPE * v.x;
    v.y = fmaf(v.y, sc.y, sh.y); v.y = v.y >= 0.f ? v.y : LRELU_SLOPE * v.y;
    v.z = fmaf(v.z, sc.z, sh.z); v.z = v.z >= 0.f ? v.z : LRELU_SLOPE * v.z;
    v.w = fmaf(v.w, sc.w, sh.w); v.w = v.w >= 0.f ? v.w : LRELU_SLOPE * v.w;
    ((float4*)out)[idx] = v;
}

// ---------------------------------------------------------------------------
extern "C" void kernel_launch(void* const* d_in, const int* in_sizes, int n_in,
                              void* d_out, int out_size)
{
    const float* x1    = (const float*)d_in[0];
    const float* x2    = (const float*)d_in[1];
    const int*   neigh = (const int*)  d_in[2];
    const int*   topi  = (const int*)  d_in[3];
    const int*   downi = (const int*)  d_in[4];
    const float* upW   = (const float*)d_in[5];
    const float* upb   = (const float*)d_in[6];
    const float* W1    = (const float*)d_in[7];
    const float* b1    = (const float*)d_in[8];
    const float* g1    = (const float*)d_in[9];
    const float* be1   = (const float*)d_in[10];
    const float* W2    = (const float*)d_in[11];
    const float* b2    = (const float*)d_in[12];
    const float* g2    = (const float*)d_in[13];
    const float* be2   = (const float*)d_in[14];
    float* out = (float*)d_out;

    cudaFuncSetAttribute(gemm_up_mma,    cudaFuncAttributeMaxDynamicSharedMemorySize, SMEM_DYN);
    cudaFuncSetAttribute(gemm_conv1_mma, cudaFuncAttributeMaxDynamicSharedMemorySize, SMEM_DYN);
    cudaFuncSetAttribute(gemm_conv2_mma, cudaFuncAttributeMaxDynamicSharedMemorySize, SMEM_DYN);

    void *yp = nullptr, *x1t = nullptr, *x2t = nullptr;
    cudaGetSymbolAddress(&yp, g_y);
    cudaGetSymbolAddress(&x1t, g_x1t);
    cudaGetSymbolAddress(&x2t, g_x2t);

    const int blkUp = (int)((MUP + 127) / 128);
    const int blkC  = (int)((MC  + 127) / 128);
    const long quads   = (long)BB * NH * 16;
    const int ewBlocks = (int)((quads + 255) / 256);
    const int pwBlocks = (143360 + 255) / 256;
    const long q1 = MUP * CIN / 4, q2 = MC * CO / 4;

    prep_weights  <<<pwBlocks, 256>>>(upW, W1, W2);
    round_tf32    <<<(int)((q1 + 255) / 256), 256>>>(x1, (float*)x1t, q1);
    round_tf32    <<<(int)((q2 + 255) / 256), 256>>>(x2, (float*)x2t, q2);
    gemm_up_mma   <<<dim3(blkUp, 7), 256, SMEM_DYN>>>(upb);
    build_xup     <<<ewBlocks, 256>>>(topi, downi);
    gemm_conv1_mma<<<blkC, 256, SMEM_DYN>>>(b1, neigh);
    reduce_stats  <<<NPART, 256>>>((const float*)yp, MC);
    bn_finalize   <<<1, 64>>>(g1, be1, 1.0f / (float)MC);
    apply_bn1_round<<<ewBlocks, 256>>>();
    gemm_conv2_mma<<<blkC, 256, SMEM_DYN>>>(b2, neigh, out);
    reduce_stats  <<<NPART, 256>>>(out, MC);
    bn_finalize   <<<1, 64>>>(g2, be2, 1.0f / (float)MC);
    apply_bn      <<<ewBlocks, 256>>>(out);
}

// round 6
// speedup vs baseline: 1.9690x; 1.1308x over previous
#include <cuda_runtime.h>
#include <cstdint>

#define LRELU_SLOPE 0.2f
#define BN_EPS 1e-5f

constexpr int  BB  = 2;
constexpr int  NR  = 40962;
constexpr int  NH  = 4 * NR - 6;      // 163842
constexpr int  CIN = 128;
constexpr int  CO  = 64;
constexpr int  NUP = 7 * CO;          // 448
constexpr long MUP = (long)BB * NR;   // 81924
constexpr long MC  = (long)BB * NH;   // 327684
constexpr int  NPART = 512;

__device__ float g_h   [(size_t)BB * NR * 7 * CO];   // up output, fp32
__device__ float g_xup [(size_t)BB * NH * CO];       // x1_up, tf32-rounded
__device__ float g_y   [(size_t)BB * NH * CO];       // conv1 out -> bn1+round in place
__device__ float g_x1t [(size_t)BB * NR * CIN];      // x1 tf32-rounded
__device__ float g_x2t [(size_t)BB * NH * CO];       // x2 tf32-rounded
__device__ float g_part[NPART * 128];
__device__ float g_bn  [128];
// Fragment-packed tf32 weights: per chunk 4096 floats,
// float4 unit index (ks*4+np)*32 + lane; unit = {nt=2np:(i0,i1), nt=2np+1:(i0,i1)}
__device__ float g_wupf[7 * 2 * 4096];
__device__ float g_w1f [14 * 4096];
__device__ float g_w2f [7 * 4096];

#define TF32R(u, f) asm("cvt.rna.tf32.f32 %0, %1;" : "=r"(u) : "f"(f))

#define MMA_TF32(d, a0, a1, a2, a3, b0, b1)                                  \
    asm volatile("mma.sync.aligned.m16n8k8.row.col.f32.tf32.tf32.f32 "       \
        "{%0,%1,%2,%3}, {%4,%5,%6,%7}, {%8,%9}, {%0,%1,%2,%3};"              \
        : "+f"((d)[0]), "+f"((d)[1]), "+f"((d)[2]), "+f"((d)[3])             \
        : "r"(a0), "r"(a1), "r"(a2), "r"(a3), "r"(b0), "r"(b1))

#define CP_ASYNC16(dst_u32, src)                                             \
    asm volatile("cp.async.cg.shared.global [%0], [%1], 16;"                 \
                 :: "r"(dst_u32), "l"(src) : "memory")
#define CP_COMMIT()  asm volatile("cp.async.commit_group;" ::: "memory")
#define CP_WAIT(n)   asm volatile("cp.async.wait_group %0;" :: "n"(n) : "memory")

constexpr int AS_STRIDE = 68;                 // 68 % 32 == 4 -> conflict-free frag reads
constexpr int AS_FLOATS = 128 * AS_STRIDE;    // per buffer (34,816 B)
constexpr int SMEM_3BUF = 3 * AS_FLOATS * 4;  // 104,448 B (conv kernels)
constexpr int SMEM_2BUF = 2 * AS_FLOATS * 4;  // 69,632 B  (up kernel)

// ---------------------------------------------------------------------------
// tf32 rounding pass
// ---------------------------------------------------------------------------
__global__ void round_tf32(const float* __restrict__ src, float* __restrict__ dst, long nquads)
{
    long i = (long)blockIdx.x * blockDim.x + threadIdx.x;
    if (i >= nquads) return;
    float4 v = ((const float4*)src)[i];
    uint32_t a, b, c, d;
    TF32R(a, v.x); TF32R(b, v.y); TF32R(c, v.z); TF32R(d, v.w);
    ((uint4*)dst)[i] = make_uint4(a, b, c, d);
}

// ---------------------------------------------------------------------------
// Weight prep: transpose + tf32 round + fragment packing
// ---------------------------------------------------------------------------
__global__ void prep_weights(const float* __restrict__ upW,
                             const float* __restrict__ W1,
                             const float* __restrict__ W2)
{
    int f = blockIdx.x * 256 + threadIdx.x;
    if (f >= 143360) return;
    int which, rel, t = 0;
    if (f < 57344)       { which = 0; rel = f; t = rel >> 13; rel &= 8191; }
    else if (f < 114688) { which = 1; rel = f - 57344; }
    else                 { which = 2; rel = f - 114688; }
    int kc = rel >> 12;
    int c  = rel & 4095;
    int q    = c & 3;
    int lane = (c >> 2) & 31;
    int np   = (c >> 7) & 3;
    int ks   = (c >> 9) & 7;
    int nt   = np * 2 + (q >> 1);
    int i    = q & 1;
    int nloc = nt * 8 + (lane >> 2);
    int k    = kc * 64 + ks * 8 + (lane & 3) + 4 * i;
    float src;
    if (which == 0)      src = upW[k * 448 + t * 64 + nloc];
    else if (which == 1) src = W1[k * 64 + nloc];
    else                 src = W2[k * 64 + nloc];
    uint32_t u; TF32R(u, src);
    if (which == 0)      g_wupf[f]         = __uint_as_float(u);
    else if (which == 1) g_w1f[f - 57344]  = __uint_as_float(u);
    else                 g_w2f[f - 114688] = __uint_as_float(u);
}

// ---------------------------------------------------------------------------
// Warp-autonomous GEMM machinery.
// Warp w owns A-rows [w*16, w*16+16): fills them, computes them. No CTA syncs.
// Fill: lane covers row w*16 + (lane>>1), half (lane&1) -> 8 x cp.async16.
// ---------------------------------------------------------------------------
#define MK_VARS()                                                             \
    extern __shared__ float sm[];                                             \
    const int tid = threadIdx.x, lane = tid & 31, warp = tid >> 5;            \
    const int frow = (warp << 4) + (lane >> 1);     /* fill row (0..127) */   \
    const int fhalf = lane & 1;                                               \
    uint32_t as_u32 = (uint32_t)__cvta_generic_to_shared(sm);                 \
    float acc[8][4];

#define MK_ACC_ZERO()                                                         \
    _Pragma("unroll") for (int i = 0; i < 8; i++)                             \
    _Pragma("unroll") for (int j = 0; j < 4; j++) acc[i][j] = 0.f;

#define MK_ISSUE(buf, rowptr)                                                 \
    {                                                                         \
        uint32_t d = as_u32 + ((buf) * AS_FLOATS + frow * AS_STRIDE + fhalf * 32) * 4; \
        const float4* s = (const float4*)(rowptr) + fhalf * 8;                \
        _Pragma("unroll")                                                     \
        for (int i = 0; i < 8; i++) CP_ASYNC16(d + i * 16, s + i);            \
        CP_COMMIT();                                                          \
    }

// B double-prefetched in registers inside the ks loop.
#define MK_COMPUTE(buf, bchunk)                                               \
    {                                                                         \
        const float* As = sm + (buf) * AS_FLOATS;                             \
        const float4* bp = (const float4*)(bchunk) + lane;                    \
        const int r0 = (warp << 4) + (lane >> 2);                             \
        const int c0 = lane & 3;                                              \
        float4 bcur[4], bnxt[4];                                              \
        _Pragma("unroll")                                                     \
        for (int np = 0; np < 4; np++) bcur[np] = __ldg(bp + np * 32);        \
        _Pragma("unroll")                                                     \
        for (int ks = 0; ks < 8; ks++) {                                      \
            if (ks < 7) {                                                     \
                _Pragma("unroll")                                             \
                for (int np = 0; np < 4; np++)                                \
                    bnxt[np] = __ldg(bp + ((ks + 1) * 4 + np) * 32);          \
            }                                                                 \
            uint32_t a0 = __float_as_uint(As[ r0      * AS_STRIDE + ks*8 + c0    ]); \
            uint32_t a1 = __float_as_uint(As[(r0 + 8) * AS_STRIDE + ks*8 + c0    ]); \
            uint32_t a2 = __float_as_uint(As[ r0      * AS_STRIDE + ks*8 + c0 + 4]); \
            uint32_t a3 = __float_as_uint(As[(r0 + 8) * AS_STRIDE + ks*8 + c0 + 4]); \
            _Pragma("unroll")                                                 \
            for (int np = 0; np < 4; np++) {                                  \
                MMA_TF32(acc[np*2],   a0, a1, a2, a3,                         \
                         __float_as_uint(bcur[np].x), __float_as_uint(bcur[np].y)); \
                MMA_TF32(acc[np*2+1], a0, a1, a2, a3,                         \
                         __float_as_uint(bcur[np].z), __float_as_uint(bcur[np].w)); \
            }                                                                 \
            _Pragma("unroll")                                                 \
            for (int np = 0; np < 4; np++) bcur[np] = bnxt[np];               \
        }                                                                     \
    }

#define MK_EPILOGUE(dst, ldc, Mlim, biasp)                                    \
    {                                                                         \
        long mr = rowBase + (warp << 4) + (lane >> 2);                        \
        int  cb = (lane & 3) * 2;                                             \
        _Pragma("unroll")                                                     \
        for (int nt = 0; nt < 8; nt++) {                                      \
            float bx = (biasp)[nt * 8 + cb];                                  \
            float by = (biasp)[nt * 8 + cb + 1];                              \
            if (mr < (Mlim)) {                                                \
                float2 v = make_float2(acc[nt][0] + bx, acc[nt][1] + by);     \
                *(float2*)((dst) + mr * (ldc) + nt * 8 + cb) = v;             \
            }                                                                 \
            if (mr + 8 < (Mlim)) {                                            \
                float2 v = make_float2(acc[nt][2] + bx, acc[nt][3] + by);     \
                *(float2*)((dst) + (mr + 8) * (ldc) + nt * 8 + cb) = v;       \
            }                                                                 \
        }                                                                     \
    }

// 3-stage pipeline over NC chunks, per-warp sync only.
#define MK_PIPELINE(NC, ROWPTR, WPTR)                                         \
    MK_ISSUE(0, ROWPTR(0));                                                   \
    MK_ISSUE(1, ROWPTR(1));                                                   \
    _Pragma("unroll 1")                                                       \
    for (int kc = 0; kc < (NC); kc++) {                                       \
        if (kc + 2 < (NC)) {                                                  \
            int nb3 = (kc + 2) % 3;                                           \
            MK_ISSUE(nb3, ROWPTR(kc + 2));                                    \
            CP_WAIT(2);                                                       \
        } else if (kc + 2 == (NC)) CP_WAIT(1);                                \
        else CP_WAIT(0);                                                      \
        __syncwarp();                                                         \
        MK_COMPUTE(kc % 3, (WPTR) + kc * 4096);                               \
    }

// ---------------------------------------------------------------------------
// GEMM 1: up-projection. A loaded once; 7 column tiles in-CTA.
// ---------------------------------------------------------------------------
__global__ __launch_bounds__(256, 2) void gemm_up_mma(const float* __restrict__ bias)
{
    MK_VARS();
    const long rowBase = (long)blockIdx.x * 128;
    long fm = rowBase + frow; if (fm >= MUP) fm = MUP - 1;
    const float* arow = g_x1t + fm * CIN;

    MK_ISSUE(0, arow);
    MK_ISSUE(1, arow + 64);
    CP_WAIT(0);
    __syncwarp();

    for (int t = 0; t < 7; t++) {
        MK_ACC_ZERO();
        MK_COMPUTE(0, g_wupf + (t * 2 + 0) * 4096);
        MK_COMPUTE(1, g_wupf + (t * 2 + 1) * 4096);
        MK_EPILOGUE(g_h + t * 64, NUP, MUP, bias + t * 64);
    }
}

// ---------------------------------------------------------------------------
// Build x1_up (writes tf32-rounded)
// ---------------------------------------------------------------------------
__global__ void build_xup(const int* __restrict__ topi, const int* __restrict__ downi)
{
    long idx = (long)blockIdx.x * blockDim.x + threadIdx.x;
    long total = (long)BB * NH * 16;
    if (idx >= total) return;
    long row = idx >> 4;
    int  q = (int)(idx & 15);
    int  b = (int)(row / NH);
    int  n = (int)(row - (long)b * NH);
    const float* hb = g_h + (long)b * NR * 7 * CO;
    float4 v;
    if (n < NR) {
        int s = __ldg(topi + n);
        v = *(const float4*)(hb + (long)s * CO + q * 4);
    } else {
        int m2 = n - NR;
        int s0 = __ldg(downi + 2 * m2);
        int s1 = __ldg(downi + 2 * m2 + 1);
        float4 a = *(const float4*)(hb + (long)s0 * CO + q * 4);
        float4 c = *(const float4*)(hb + (long)s1 * CO + q * 4);
        v = make_float4(0.5f * (a.x + c.x), 0.5f * (a.y + c.y),
                        0.5f * (a.z + c.z), 0.5f * (a.w + c.w));
    }
    uint32_t a_, b_, c_, d_;
    TF32R(a_, v.x); TF32R(b_, v.y); TF32R(c_, v.z); TF32R(d_, v.w);
    *(uint4*)(g_xup + row * CO + q * 4) = make_uint4(a_, b_, c_, d_);
}

// ---------------------------------------------------------------------------
// GEMM 2: conv1 (gathered A from g_xup / g_x2t). 14 chunks.
// ---------------------------------------------------------------------------
__global__ __launch_bounds__(256, 2) void gemm_conv1_mma(const float* __restrict__ bias,
                                                         const int* __restrict__ neigh)
{
    MK_VARS();
    MK_ACC_ZERO();
    const long rowBase = (long)blockIdx.x * 128;
    long fm = rowBase + frow; if (fm >= MC) fm = MC - 1;
    const int  fb = (int)(fm / NH);
    const int  fn = (int)(fm - (long)fb * NH);
    const long bbase = (long)fb * NH;
    int nidx[7];
#pragma unroll
    for (int j = 0; j < 7; j++) nidx[j] = __ldg(neigh + (long)fn * 7 + j);

#define C1_ROW(kc) (((kc) & 1 ? g_x2t : g_xup) + (bbase + nidx[(kc) >> 1]) * CO)
    MK_PIPELINE(14, C1_ROW, g_w1f);
#undef C1_ROW
    MK_EPILOGUE(g_y, CO, MC, bias);
}

// ---------------------------------------------------------------------------
// GEMM 3: conv2 (gathered A from g_y, bn1+lrelu+tf32 already applied). 7 chunks.
// ---------------------------------------------------------------------------
__global__ __launch_bounds__(256, 2) void gemm_conv2_mma(const float* __restrict__ bias,
                                                         const int* __restrict__ neigh,
                                                         float* __restrict__ out)
{
    MK_VARS();
    MK_ACC_ZERO();
    const long rowBase = (long)blockIdx.x * 128;
    long fm = rowBase + frow; if (fm >= MC) fm = MC - 1;
    const int  fb = (int)(fm / NH);
    const int  fn = (int)(fm - (long)fb * NH);
    const long bbase = (long)fb * NH;
    int nidx[7];
#pragma unroll
    for (int j = 0; j < 7; j++) nidx[j] = __ldg(neigh + (long)fn * 7 + j);

#define C2_ROW(kc) (g_y + (bbase + nidx[kc]) * CO)
    MK_PIPELINE(7, C2_ROW, g_w2f);
#undef C2_ROW
    MK_EPILOGUE(out, CO, MC, bias);
}

// ---------------------------------------------------------------------------
// BN statistics / finalize / elementwise
// ---------------------------------------------------------------------------
__global__ __launch_bounds__(256) void reduce_stats(const float* __restrict__ data, long Mrows)
{
    __shared__ float4 sh_s [16][16];
    __shared__ float4 sh_ss[16][16];
    int q  = threadIdx.x & 15;
    int rg = threadIdx.x >> 4;
    float4 s  = make_float4(0.f, 0.f, 0.f, 0.f);
    float4 ss = make_float4(0.f, 0.f, 0.f, 0.f);
    for (long r = (long)blockIdx.x * 16 + rg; r < Mrows; r += (long)gridDim.x * 16) {
        float4 v = *(const float4*)(data + r * 64 + q * 4);
        s.x += v.x; s.y += v.y; s.z += v.z; s.w += v.w;
        ss.x = fmaf(v.x, v.x, ss.x); ss.y = fmaf(v.y, v.y, ss.y);
        ss.z = fmaf(v.z, v.z, ss.z); ss.w = fmaf(v.w, v.w, ss.w);
    }
    sh_s[rg][q] = s; sh_ss[rg][q] = ss;
    __syncthreads();
#pragma unroll
    for (int stride = 8; stride >= 1; stride >>= 1) {
        if (rg < stride) {
            float4 a = sh_s[rg][q], b = sh_s[rg + stride][q];
            a.x += b.x; a.y += b.y; a.z += b.z; a.w += b.w;
            sh_s[rg][q] = a;
            float4 c = sh_ss[rg][q], d = sh_ss[rg + stride][q];
            c.x += d.x; c.y += d.y; c.z += d.z; c.w += d.w;
            sh_ss[rg][q] = c;
        }
        __syncthreads();
    }
    if (rg == 0) {
        *(float4*)(g_part + blockIdx.x * 128 + q * 4)      = sh_s[0][q];
        *(float4*)(g_part + blockIdx.x * 128 + 64 + q * 4) = sh_ss[0][q];
    }
}

__global__ void bn_finalize(const float* __restrict__ gamma,
                            const float* __restrict__ beta, float invM)
{
    int c = threadIdx.x;
    float s = 0.f, ss = 0.f;
    for (int p = 0; p < NPART; p++) {
        s  += g_part[p * 128 + c];
        ss += g_part[p * 128 + 64 + c];
    }
    float mean = s * invM;
    float var  = fmaf(-mean, mean, ss * invM);
    float sc   = gamma[c] * rsqrtf(var + BN_EPS);
    g_bn[c]      = sc;
    g_bn[64 + c] = beta[c] - mean * sc;
}

__global__ void apply_bn1_round()
{
    long idx = (long)blockIdx.x * blockDim.x + threadIdx.x;
    if (idx >= MC * 16) return;
    int q = (int)(idx & 15);
    float4 v  = ((float4*)g_y)[idx];
    float4 sc = *(const float4*)&g_bn[q * 4];
    float4 sh = *(const float4*)&g_bn[64 + q * 4];
    v.x = fmaf(v.x, sc.x, sh.x); v.x = v.x >= 0.f ? v.x : LRELU_SLOPE * v.x;
    v.y = fmaf(v.y, sc.y, sh.y); v.y = v.y >= 0.f ? v.y : LRELU_SLOPE * v.y;
    v.z = fmaf(v.z, sc.z, sh.z); v.z = v.z >= 0.f ? v.z : LRELU_SLOPE * v.z;
    v.w = fmaf(v.w, sc.w, sh.w); v.w = v.w >= 0.f ? v.w : LRELU_SLOPE * v.w;
    uint32_t a, b, c, d;
    TF32R(a, v.x); TF32R(b, v.y); TF32R(c, v.z); TF32R(d, v.w);
    ((uint4*)g_y)[idx] = make_uint4(a, b, c, d);
}

__global__ void apply_bn(float* __restrict__ out)
{
    long idx = (long)blockIdx.x * blockDim.x + threadIdx.x;
    if (idx >= MC * 16) return;
    int q = (int)(idx & 15);
    float4 v  = ((float4*)out)[idx];
    float4 sc = *(const float4*)&g_bn[q * 4];
    float4 sh = *(const float4*)&g_bn[64 + q * 4];
    v.x = fmaf(v.x, sc.x, sh.x); v.x = v.x >= 0.f ? v.x : LRELU_SLOPE * v.x;
    v.y = fmaf(v.y, sc.y, sh.y); v.y = v.y >= 0.f ? v.y : LRELU_SLOPE * v.y;
    v.z = fmaf(v.z, sc.z, sh.z); v.z = v.z >= 0.f ? v.z : LRELU_SLOPE * v.z;
    v.w = fmaf(v.w, sc.w, sh.w); v.w = v.w >= 0.f ? v.w : LRELU_SLOPE * v.w;
    ((float4*)out)[idx] = v;
}

// ---------------------------------------------------------------------------
extern "C" void kernel_launch(void* const* d_in, const int* in_sizes, int n_in,
                              void* d_out, int out_size)
{
    const float* x1    = (const float*)d_in[0];
    const float* x2    = (const float*)d_in[1];
    const int*   neigh = (const int*)  d_in[2];
    const int*   topi  = (const int*)  d_in[3];
    const int*   downi = (const int*)  d_in[4];
    const float* upW   = (const float*)d_in[5];
    const float* upb   = (const float*)d_in[6];
    const float* W1    = (const float*)d_in[7];
    const float* b1    = (const float*)d_in[8];
    const float* g1    = (const float*)d_in[9];
    const float* be1   = (const float*)d_in[10];
    const float* W2    = (const float*)d_in[11];
    const float* b2    = (const float*)d_in[12];
    const float* g2    = (const float*)d_in[13];
    const float* be2   = (const float*)d_in[14];
    float* out = (float*)d_out;

    cudaFuncSetAttribute(gemm_up_mma,    cudaFuncAttributeMaxDynamicSharedMemorySize, SMEM_2BUF);
    cudaFuncSetAttribute(gemm_conv1_mma, cudaFuncAttributeMaxDynamicSharedMemorySize, SMEM_3BUF);
    cudaFuncSetAttribute(gemm_conv2_mma, cudaFuncAttributeMaxDynamicSharedMemorySize, SMEM_3BUF);

    void *yp = nullptr, *x1t = nullptr, *x2t = nullptr;
    cudaGetSymbolAddress(&yp, g_y);
    cudaGetSymbolAddress(&x1t, g_x1t);
    cudaGetSymbolAddress(&x2t, g_x2t);

    const int blkUp = (int)((MUP + 127) / 128);
    const int blkC  = (int)((MC  + 127) / 128);
    const long quads   = (long)BB * NH * 16;
    const int ewBlocks = (int)((quads + 255) / 256);
    const int pwBlocks = (143360 + 255) / 256;
    const long q1 = MUP * CIN / 4, q2 = MC * CO / 4;

    prep_weights  <<<pwBlocks, 256>>>(upW, W1, W2);
    round_tf32    <<<(int)((q1 + 255) / 256), 256>>>(x1, (float*)x1t, q1);
    round_tf32    <<<(int)((q2 + 255) / 256), 256>>>(x2, (float*)x2t, q2);
    gemm_up_mma   <<<blkUp, 256, SMEM_2BUF>>>(upb);
    build_xup     <<<ewBlocks, 256>>>(topi, downi);
    gemm_conv1_mma<<<blkC, 256, SMEM_3BUF>>>(b1, neigh);
    reduce_stats  <<<NPART, 256>>>((const float*)yp, MC);
    bn_finalize   <<<1, 64>>>(g1, be1, 1.0f / (float)MC);
    apply_bn1_round<<<ewBlocks, 256>>>();
    gemm_conv2_mma<<<blkC, 256, SMEM_3BUF>>>(b2, neigh, out);
    reduce_stats  <<<NPART, 256>>>(out, MC);
    bn_finalize   <<<1, 64>>>(g2, be2, 1.0f / (float)MC);
    apply_bn      <<<ewBlocks, 256>>>(out);
}